// round 3
// baseline (speedup 1.0000x reference)
#include <cuda_runtime.h>
#include <cstdint>

// Problem constants (fixed for this instance):
//   logits:  [B=256, VOCAB=128000] float32
//   save_id: [B=256, HIST=512] int32  (JAX x64 disabled -> int64 request decays to int32)
//   penalty_value: [1] float32
//   penalty_range: 64
#define B_DIM      256
#define VOCAB_DIM  128000
#define HIST_DIM   512
#define PEN_RANGE  64

// Bulk copy logits -> out, 16B vectorized, grid-stride.
__global__ void copy_logits_vec4(const float4* __restrict__ src,
                                 float4* __restrict__ dst,
                                 size_t n4) {
    size_t i      = (size_t)blockIdx.x * blockDim.x + threadIdx.x;
    size_t stride = (size_t)gridDim.x * blockDim.x;
    for (; i < n4; i += stride)
        dst[i] = src[i];
}

// Scatter: for each (row, j) in [256, 64]:
//   out[row, id] = logits[row, id] * p,  id = save_id[row, HIST-64 + j]
// Duplicate ids are idempotent (value depends only on the original logit).
__global__ void apply_penalty_scatter(const float* __restrict__ logits,
                                      const int* __restrict__ save_id,
                                      const float* __restrict__ penalty,
                                      float* __restrict__ out) {
    const float p = penalty[0];
    int tid = blockIdx.x * blockDim.x + threadIdx.x;   // 0 .. 256*64-1
    int row = tid >> 6;
    int j   = tid & 63;
    if (row >= B_DIM) return;
    int id = save_id[row * HIST_DIM + (HIST_DIM - PEN_RANGE) + j];
    if ((unsigned)id < (unsigned)VOCAB_DIM) {          // defensive: never OOB
        size_t off = (size_t)row * VOCAB_DIM + (size_t)id;
        out[off] = logits[off] * p;
    }
}

extern "C" void kernel_launch(void* const* d_in, const int* in_sizes, int n_in,
                              void* d_out, int out_size) {
    const float* logits  = (const float*)d_in[0];
    const int*   save_id = (const int*)d_in[1];
    const float* penalty = (const float*)d_in[2];
    float*       out     = (float*)d_out;

    // 1) Bulk copy. Element count from the harness (robust to assumptions);
    //    B*VOCAB = 32,768,000 is divisible by 4, so vec4 covers it exactly.
    {
        size_t total = (size_t)in_sizes[0];
        size_t n4    = total >> 2;
        const int threads = 512;
        const int blocks  = 2048;   // ~7.8 vec4 iters/thread: ample MLP, even waves
        copy_logits_vec4<<<blocks, threads>>>(
            (const float4*)logits, (float4*)out, n4);
        // Tail (not expected for this shape, but keep exactness if total%4 != 0)
        // handled implicitly: total is 32768000 -> no tail.
    }

    // 2) Scatter penalized entries (same stream -> ordered after the copy).
    {
        const int threads = 256;
        const int blocks  = (B_DIM * PEN_RANGE + threads - 1) / threads;  // 64
        apply_penalty_scatter<<<blocks, threads>>>(logits, save_id, penalty, out);
    }
}

// round 4
// speedup vs baseline: 1.0916x; 1.0916x over previous
#include <cuda_runtime.h>
#include <cstdint>

// Problem constants (fixed for this instance):
//   logits:  [B=256, VOCAB=128000] float32
//   save_id: [B=256, HIST=512] int32 (JAX x64 disabled)
//   penalty_value: [1] float32
//   penalty_range: 64
#define B_DIM      256
#define VOCAB_DIM  128000
#define HIST_DIM   512
#define PEN_RANGE  64

// Row = 32000 float4. Split into 25 segments of 1280 float4 (5120 floats).
#define ROW_F4        32000
#define SEGS_PER_ROW  25
#define SEG_F4        1280      // = ROW_F4 / SEGS_PER_ROW
#define SEG_FLOATS    (SEG_F4 * 4)   // 5120
#define THREADS       256
#define F4_PER_THREAD 5         // 256 * 5 = 1280

// Fused copy + penalty fixup.
// Each block copies one 5120-float segment of one row, then threads 0..63
// check that row's 64 penalized ids; ids landing in this segment get
// out = logits * p (idempotent for duplicates; __syncthreads orders the
// fixup stores after the copy stores).
__global__ void __launch_bounds__(THREADS)
apply_penalty_fused(const float4* __restrict__ logits4,
                    const float*  __restrict__ logits,
                    const int*    __restrict__ save_id,
                    const float*  __restrict__ penalty,
                    float4* __restrict__ out4,
                    float*  __restrict__ out) {
    const int b   = blockIdx.x;
    const int row = b / SEGS_PER_ROW;
    const int seg = b - row * SEGS_PER_ROW;

    // ---- copy phase: 1280 float4, coalesced, 5 per thread ----
    const size_t base4 = (size_t)row * ROW_F4 + (size_t)seg * SEG_F4;
    #pragma unroll
    for (int i = 0; i < F4_PER_THREAD; i++) {
        size_t idx = base4 + (size_t)i * THREADS + threadIdx.x;
        out4[idx] = logits4[idx];
    }

    __syncthreads();   // copy stores ordered before fixup stores (block scope)

    // ---- fixup phase: threads 0..63 check this row's penalized ids ----
    if (threadIdx.x < PEN_RANGE) {
        const int lo = seg * SEG_FLOATS;
        const int hi = lo + SEG_FLOATS;
        int id = save_id[row * HIST_DIM + (HIST_DIM - PEN_RANGE) + threadIdx.x];
        if (id >= lo && id < hi) {
            const float p = penalty[0];
            size_t off = (size_t)row * VOCAB_DIM + (size_t)id;
            out[off] = logits[off] * p;
        }
    }
}

extern "C" void kernel_launch(void* const* d_in, const int* in_sizes, int n_in,
                              void* d_out, int out_size) {
    const float* logits  = (const float*)d_in[0];
    const int*   save_id = (const int*)d_in[1];
    const float* penalty = (const float*)d_in[2];
    float*       out     = (float*)d_out;

    const int blocks = B_DIM * SEGS_PER_ROW;   // 6400
    apply_penalty_fused<<<blocks, THREADS>>>(
        (const float4*)logits, logits, save_id, penalty,
        (float4*)out, out);
}

// round 5
// speedup vs baseline: 1.0994x; 1.0072x over previous
#include <cuda_runtime.h>
#include <cstdint>

// Problem constants (fixed for this instance):
//   logits:  [B=256, VOCAB=128000] float32
//   save_id: [B=256, HIST=512] int32 (JAX x64 disabled)
//   penalty_value: [1] float32
//   penalty_range: 64
#define B_DIM      256
#define VOCAB_DIM  128000
#define HIST_DIM   512
#define PEN_RANGE  64

// Row = 32000 float4. Split into 25 segments of 1280 float4 (5120 floats).
#define ROW_F4        32000
#define SEGS_PER_ROW  25
#define SEG_F4        1280
#define SEG_FLOATS    (SEG_F4 * 4)   // 5120
#define THREADS       256
#define F4_PER_THREAD 5              // 256 * 5 = 1280

// Fused copy + penalty fixup, with streaming (evict-first) cache hints and
// front-batched loads for maximum per-warp MLP.
__global__ void __launch_bounds__(THREADS)
apply_penalty_fused(const float4* __restrict__ logits4,
                    const float*  __restrict__ logits,
                    const int*    __restrict__ save_id,
                    const float*  __restrict__ penalty,
                    float4* __restrict__ out4,
                    float*  __restrict__ out) {
    const int b   = blockIdx.x;
    const int row = b / SEGS_PER_ROW;
    const int seg = b - row * SEGS_PER_ROW;

    // ---- copy phase: batch all 5 loads, then all 5 stores (streaming) ----
    const size_t base4 = (size_t)row * ROW_F4 + (size_t)seg * SEG_F4 + threadIdx.x;
    float4 v[F4_PER_THREAD];
    #pragma unroll
    for (int i = 0; i < F4_PER_THREAD; i++)
        v[i] = __ldcs(&logits4[base4 + (size_t)i * THREADS]);
    #pragma unroll
    for (int i = 0; i < F4_PER_THREAD; i++)
        __stcs(&out4[base4 + (size_t)i * THREADS], v[i]);

    __syncthreads();   // copy stores ordered before fixup stores (block scope)

    // ---- fixup phase: threads 0..63 check this row's penalized ids ----
    if (threadIdx.x < PEN_RANGE) {
        const int lo = seg * SEG_FLOATS;
        const int hi = lo + SEG_FLOATS;
        int id = save_id[row * HIST_DIM + (HIST_DIM - PEN_RANGE) + threadIdx.x];
        if (id >= lo && id < hi) {
            const float p = penalty[0];
            size_t off = (size_t)row * VOCAB_DIM + (size_t)id;
            out[off] = logits[off] * p;   // L2-hit read; tiny scattered store
        }
    }
}

extern "C" void kernel_launch(void* const* d_in, const int* in_sizes, int n_in,
                              void* d_out, int out_size) {
    const float* logits  = (const float*)d_in[0];
    const int*   save_id = (const int*)d_in[1];
    const float* penalty = (const float*)d_in[2];
    float*       out     = (float*)d_out;

    const int blocks = B_DIM * SEGS_PER_ROW;   // 6400
    apply_penalty_fused<<<blocks, THREADS>>>(
        (const float4*)logits, logits, save_id, penalty,
        (float4*)out, out);
}